// round 3
// baseline (speedup 1.0000x reference)
#include <cuda_runtime.h>
#include <cstdint>

#define NUM_HEADS 16
#define SEQ 2048
#define HDIM 64
#define HID 1024
#define BATCH 2
#define M_TOTAL (BATCH * SEQ)      // 4096
#define BH (BATCH * NUM_HEADS)     // 32
#define SCALE 0.125f               // 1/sqrt(64)

// Scratch (no cudaMalloc allowed): 96 MB total
__device__ float g_QP [(size_t)BH * SEQ * 128];   // [b,h,s, 0:64]=Q, [64:128]=P
__device__ float g_KPK[(size_t)BH * SEQ * 128];   // [b,h,s, 0:64]=K+P, [64:128]=K
__device__ float g_V  [(size_t)BH * SEQ * HDIM];  // [b,h,s,d]
__device__ float g_O  [(size_t)M_TOTAL * HID];    // [b,s,h*64+d]

// ---------------------------------------------------------------------------
// NT GEMM with bias: C[m,n] = sum_k X[m,k]*W[n,k] + bias[n]
// M=4096, N=1024, K=1024. BM=BN=128, BK=16. 256 threads, 8x8 per thread.
// mode 0: dst[m*HID + n]                          (final output)
// mode 1: dst[((b*16+h)*SEQ+s)*128 + off + d]     (QP / KPK head layout)
// mode 2: dst[((b*16+h)*SEQ+s)*64 + d]            (V head layout)
// ---------------------------------------------------------------------------
__global__ __launch_bounds__(256) void gemm_proj(
    const float* __restrict__ X, const float* __restrict__ W,
    const float* __restrict__ bias, float* __restrict__ dst,
    int mode, int off)
{
    __shared__ float As[16][128];
    __shared__ float Bs[16][128];
    const int tid = threadIdx.x;
    const int tx = tid & 15, ty = tid >> 4;
    const int m0 = blockIdx.y * 128, n0 = blockIdx.x * 128;

    float acc[8][8];
#pragma unroll
    for (int i = 0; i < 8; i++)
#pragma unroll
        for (int j = 0; j < 8; j++) acc[i][j] = 0.f;

    for (int kt = 0; kt < 1024; kt += 16) {
#pragma unroll
        for (int l = 0; l < 2; l++) {
            int lin = tid + l * 256;             // [0,512)
            int row = lin >> 2, c4 = lin & 3;
            float4 a = *(const float4*)(X + (size_t)(m0 + row) * 1024 + kt + c4 * 4);
            As[c4 * 4 + 0][row] = a.x; As[c4 * 4 + 1][row] = a.y;
            As[c4 * 4 + 2][row] = a.z; As[c4 * 4 + 3][row] = a.w;
            float4 b = *(const float4*)(W + (size_t)(n0 + row) * 1024 + kt + c4 * 4);
            Bs[c4 * 4 + 0][row] = b.x; Bs[c4 * 4 + 1][row] = b.y;
            Bs[c4 * 4 + 2][row] = b.z; Bs[c4 * 4 + 3][row] = b.w;
        }
        __syncthreads();
#pragma unroll
        for (int k = 0; k < 16; k++) {
            float a[8], b[8];
#pragma unroll
            for (int i = 0; i < 8; i++) a[i] = As[k][ty * 8 + i];
#pragma unroll
            for (int j = 0; j < 8; j++) b[j] = Bs[k][tx * 8 + j];
#pragma unroll
            for (int i = 0; i < 8; i++)
#pragma unroll
                for (int j = 0; j < 8; j++) acc[i][j] += a[i] * b[j];
        }
        __syncthreads();
    }

#pragma unroll
    for (int i = 0; i < 8; i++) {
        int m = m0 + ty * 8 + i;
#pragma unroll
        for (int j = 0; j < 8; j++) {
            int n = n0 + tx * 8 + j;
            float v = acc[i][j] + bias[n];
            if (mode == 0) {
                dst[(size_t)m * HID + n] = v;
            } else {
                int b = m >> 11, s = m & 2047;
                int h = n >> 6, d = n & 63;
                if (mode == 1)
                    dst[(((size_t)(b * NUM_HEADS + h) * SEQ + s) * 128) + off + d] = v;
                else
                    dst[(((size_t)(b * NUM_HEADS + h) * SEQ + s) * 64) + d] = v;
            }
        }
    }
}

// KPK[...,0:64] = K (stored at 64:) + P (stored in QP at 64:)
__global__ __launch_bounds__(256) void kp_add()
{
    size_t i = (size_t)blockIdx.x * 256 + threadIdx.x;  // over BH*SEQ*64
    size_t r = i >> 6, d = i & 63;
    g_KPK[r * 128 + d] = g_KPK[r * 128 + 64 + d] + g_QP[r * 128 + 64 + d];
}

// ---------------------------------------------------------------------------
// Scores: per (b,h), S[q,k] = (QP[q,:] . KPK[k,:]) * SCALE + mask[q,k]
// 2048x2048, K=128. Same 128x128x16 tiling. Writes raw (pre-softmax) scores.
// ---------------------------------------------------------------------------
__global__ __launch_bounds__(256) void gemm_scores(
    const float* __restrict__ mask, float* __restrict__ weights)
{
    const int bh = blockIdx.z;
    const float* A = g_QP  + (size_t)bh * SEQ * 128;
    const float* B = g_KPK + (size_t)bh * SEQ * 128;
    float* C = weights + (size_t)bh * SEQ * SEQ;

    __shared__ float As[16][128];
    __shared__ float Bs[16][128];
    const int tid = threadIdx.x;
    const int tx = tid & 15, ty = tid >> 4;
    const int m0 = blockIdx.y * 128, n0 = blockIdx.x * 128;

    float acc[8][8];
#pragma unroll
    for (int i = 0; i < 8; i++)
#pragma unroll
        for (int j = 0; j < 8; j++) acc[i][j] = 0.f;

    for (int kt = 0; kt < 128; kt += 16) {
#pragma unroll
        for (int l = 0; l < 2; l++) {
            int lin = tid + l * 256;
            int row = lin >> 2, c4 = lin & 3;
            float4 a = *(const float4*)(A + (size_t)(m0 + row) * 128 + kt + c4 * 4);
            As[c4 * 4 + 0][row] = a.x; As[c4 * 4 + 1][row] = a.y;
            As[c4 * 4 + 2][row] = a.z; As[c4 * 4 + 3][row] = a.w;
            float4 b = *(const float4*)(B + (size_t)(n0 + row) * 128 + kt + c4 * 4);
            Bs[c4 * 4 + 0][row] = b.x; Bs[c4 * 4 + 1][row] = b.y;
            Bs[c4 * 4 + 2][row] = b.z; Bs[c4 * 4 + 3][row] = b.w;
        }
        __syncthreads();
#pragma unroll
        for (int k = 0; k < 16; k++) {
            float a[8], b[8];
#pragma unroll
            for (int i = 0; i < 8; i++) a[i] = As[k][ty * 8 + i];
#pragma unroll
            for (int j = 0; j < 8; j++) b[j] = Bs[k][tx * 8 + j];
#pragma unroll
            for (int i = 0; i < 8; i++)
#pragma unroll
                for (int j = 0; j < 8; j++) acc[i][j] += a[i] * b[j];
        }
        __syncthreads();
    }

#pragma unroll
    for (int i = 0; i < 8; i++) {
        int q = m0 + ty * 8 + i;
#pragma unroll
        for (int j = 0; j < 8; j++) {
            int k = n0 + tx * 8 + j;
            C[(size_t)q * SEQ + k] = acc[i][j] * SCALE + mask[(size_t)q * SEQ + k];
        }
    }
}

// In-place row softmax over 2048 cols. One block (256 thr) per row.
__global__ __launch_bounds__(256) void softmax_rows(float* __restrict__ w)
{
    __shared__ float red[256];
    const size_t row = blockIdx.x;
    float* p = w + row * (size_t)SEQ;
    const int tid = threadIdx.x;

    float v[8];
    float mx = -1e30f;
#pragma unroll
    for (int i = 0; i < 8; i++) {
        v[i] = p[tid + i * 256];
        mx = fmaxf(mx, v[i]);
    }
    red[tid] = mx;
    __syncthreads();
    for (int s = 128; s > 0; s >>= 1) {
        if (tid < s) red[tid] = fmaxf(red[tid], red[tid + s]);
        __syncthreads();
    }
    mx = red[0];
    __syncthreads();

    float sum = 0.f;
#pragma unroll
    for (int i = 0; i < 8; i++) {
        v[i] = __expf(v[i] - mx);
        sum += v[i];
    }
    red[tid] = sum;
    __syncthreads();
    for (int s = 128; s > 0; s >>= 1) {
        if (tid < s) red[tid] += red[tid + s];
        __syncthreads();
    }
    float inv = 1.f / red[0];
#pragma unroll
    for (int i = 0; i < 8; i++) p[tid + i * 256] = v[i] * inv;
}

// ---------------------------------------------------------------------------
// AV: per (b,h), O[q,d] = sum_k W[q,k]*V[k,d].  M=2048, N=64, K=2048.
// BM=128, BN=64, BK=32. 256 threads, 8x4 per thread. O stored [b,s,h*64+d].
// ---------------------------------------------------------------------------
__global__ __launch_bounds__(256) void gemm_av(const float* __restrict__ weights)
{
    const int bh = blockIdx.y;
    const int b = bh >> 4, h = bh & 15;
    const float* Wm = weights + (size_t)bh * SEQ * SEQ;
    const float* V  = g_V + (size_t)bh * SEQ * HDIM;

    __shared__ float Ws[32][128];
    __shared__ float Vs[32][64];
    const int tid = threadIdx.x;
    const int tx = tid & 15, ty = tid >> 4;
    const int m0 = blockIdx.x * 128;

    float acc[8][4];
#pragma unroll
    for (int i = 0; i < 8; i++)
#pragma unroll
        for (int j = 0; j < 4; j++) acc[i][j] = 0.f;

    for (int kt = 0; kt < SEQ; kt += 32) {
#pragma unroll
        for (int l = 0; l < 4; l++) {
            int lin = tid + l * 256;             // [0,1024)
            int row = lin >> 3, c4 = lin & 7;
            float4 a = *(const float4*)(Wm + (size_t)(m0 + row) * SEQ + kt + c4 * 4);
            Ws[c4 * 4 + 0][row] = a.x; Ws[c4 * 4 + 1][row] = a.y;
            Ws[c4 * 4 + 2][row] = a.z; Ws[c4 * 4 + 3][row] = a.w;
        }
#pragma unroll
        for (int l = 0; l < 2; l++) {
            int lin = tid + l * 256;             // [0,512)
            int row = lin >> 4, c4 = lin & 15;
            *(float4*)&Vs[row][c4 * 4] =
                *(const float4*)(V + (size_t)(kt + row) * HDIM + c4 * 4);
        }
        __syncthreads();
#pragma unroll
        for (int k = 0; k < 32; k++) {
            float a[8], bb[4];
#pragma unroll
            for (int i = 0; i < 8; i++) a[i] = Ws[k][ty * 8 + i];
#pragma unroll
            for (int j = 0; j < 4; j++) bb[j] = Vs[k][tx * 4 + j];
#pragma unroll
            for (int i = 0; i < 8; i++)
#pragma unroll
                for (int j = 0; j < 4; j++) acc[i][j] += a[i] * bb[j];
        }
        __syncthreads();
    }

#pragma unroll
    for (int i = 0; i < 8; i++) {
        int s = m0 + ty * 8 + i;
#pragma unroll
        for (int j = 0; j < 4; j++) {
            int d = tx * 4 + j;
            g_O[(size_t)b * SEQ * HID + (size_t)s * HID + h * 64 + d] = acc[i][j];
        }
    }
}

// ---------------------------------------------------------------------------
extern "C" void kernel_launch(void* const* d_in, const int* in_sizes, int n_in,
                              void* d_out, int out_size)
{
    const float* q    = (const float*)d_in[0];
    const float* k    = (const float*)d_in[1];
    const float* v    = (const float*)d_in[2];
    const float* pos  = (const float*)d_in[3];
    const float* mask = (const float*)d_in[4];
    const float* Wq = (const float*)d_in[5];  const float* bq = (const float*)d_in[6];
    const float* Wk = (const float*)d_in[7];  const float* bk = (const float*)d_in[8];
    const float* Wv = (const float*)d_in[9];  const float* bv = (const float*)d_in[10];
    const float* Wp = (const float*)d_in[11]; const float* bp = (const float*)d_in[12];
    const float* Wo = (const float*)d_in[13]; const float* bo = (const float*)d_in[14];

    float* out = (float*)d_out;
    float* weights = out + (size_t)BATCH * SEQ * HID;   // out first, then weights

    float *QP, *KPK, *Vd, *O;
    cudaGetSymbolAddress((void**)&QP,  g_QP);
    cudaGetSymbolAddress((void**)&KPK, g_KPK);
    cudaGetSymbolAddress((void**)&Vd,  g_V);
    cudaGetSymbolAddress((void**)&O,   g_O);

    dim3 blk(256);
    dim3 gproj(HID / 128, M_TOTAL / 128);   // (8, 32)

    gemm_proj<<<gproj, blk>>>(q,   Wq, bq, QP,  1, 0);   // Q  -> QP[:,0:64]
    gemm_proj<<<gproj, blk>>>(pos, Wp, bp, QP,  1, 64);  // P  -> QP[:,64:128]
    gemm_proj<<<gproj, blk>>>(k,   Wk, bk, KPK, 1, 64);  // K  -> KPK[:,64:128]
    gemm_proj<<<gproj, blk>>>(v,   Wv, bv, Vd,  2, 0);   // V

    kp_add<<<(BH * SEQ * 64) / 256, blk>>>();            // KPK[:,0:64] = K + P

    dim3 gsc(SEQ / 128, SEQ / 128, BH);                  // (16,16,32)
    gemm_scores<<<gsc, blk>>>(mask, weights);

    softmax_rows<<<BH * SEQ, blk>>>(weights);

    gemm_av<<<dim3(SEQ / 128, BH), blk>>>(weights);

    gemm_proj<<<gproj, blk>>>(O, Wo, bo, out, 0, 0);     // final projection
}

// round 4
// speedup vs baseline: 1.0010x; 1.0010x over previous
#include <cuda_runtime.h>
#include <cstdint>

#define NUM_HEADS 16
#define SEQ 2048
#define HDIM 64
#define HID 1024
#define BATCH 2
#define M_TOTAL (BATCH * SEQ)      // 4096
#define BH (BATCH * NUM_HEADS)     // 32
#define SCALE 0.125f               // 1/sqrt(64)

// Scratch (no cudaMalloc allowed): 96 MB total
__device__ float g_QP [(size_t)BH * SEQ * 128];   // [b,h,s, 0:64]=Q, [64:128]=P
__device__ float g_KPK[(size_t)BH * SEQ * 128];   // [b,h,s, 0:64]=K+P, [64:128]=K
__device__ float g_V  [(size_t)BH * SEQ * HDIM];  // [b,h,s,d]
__device__ float g_O  [(size_t)M_TOTAL * HID];    // [b,s,h*64+d]

// ---------------------------------------------------------------------------
// NT GEMM with bias: C[m,n] = sum_k X[m,k]*W[n,k] + bias[n]
// M=4096, N=1024, K=1024. BM=BN=128, BK=16. 256 threads, 8x8 per thread.
// mode 0: dst[m*HID + n]                          (final output)
// mode 1: dst[((b*16+h)*SEQ+s)*128 + off + d]     (QP / KPK head layout)
// mode 2: dst[((b*16+h)*SEQ+s)*64 + d]            (V head layout)
// ---------------------------------------------------------------------------
__global__ __launch_bounds__(256) void gemm_proj(
    const float* __restrict__ X, const float* __restrict__ W,
    const float* __restrict__ bias, float* __restrict__ dst,
    int mode, int off)
{
    __shared__ float As[16][128];
    __shared__ float Bs[16][128];
    const int tid = threadIdx.x;
    const int tx = tid & 15, ty = tid >> 4;
    const int m0 = blockIdx.y * 128, n0 = blockIdx.x * 128;

    float acc[8][8];
#pragma unroll
    for (int i = 0; i < 8; i++)
#pragma unroll
        for (int j = 0; j < 8; j++) acc[i][j] = 0.f;

    for (int kt = 0; kt < 1024; kt += 16) {
#pragma unroll
        for (int l = 0; l < 2; l++) {
            int lin = tid + l * 256;             // [0,512)
            int row = lin >> 2, c4 = lin & 3;
            float4 a = *(const float4*)(X + (size_t)(m0 + row) * 1024 + kt + c4 * 4);
            As[c4 * 4 + 0][row] = a.x; As[c4 * 4 + 1][row] = a.y;
            As[c4 * 4 + 2][row] = a.z; As[c4 * 4 + 3][row] = a.w;
            float4 b = *(const float4*)(W + (size_t)(n0 + row) * 1024 + kt + c4 * 4);
            Bs[c4 * 4 + 0][row] = b.x; Bs[c4 * 4 + 1][row] = b.y;
            Bs[c4 * 4 + 2][row] = b.z; Bs[c4 * 4 + 3][row] = b.w;
        }
        __syncthreads();
#pragma unroll
        for (int k = 0; k < 16; k++) {
            float a[8], b[8];
#pragma unroll
            for (int i = 0; i < 8; i++) a[i] = As[k][ty * 8 + i];
#pragma unroll
            for (int j = 0; j < 8; j++) b[j] = Bs[k][tx * 8 + j];
#pragma unroll
            for (int i = 0; i < 8; i++)
#pragma unroll
                for (int j = 0; j < 8; j++) acc[i][j] += a[i] * b[j];
        }
        __syncthreads();
    }

#pragma unroll
    for (int i = 0; i < 8; i++) {
        int m = m0 + ty * 8 + i;
#pragma unroll
        for (int j = 0; j < 8; j++) {
            int n = n0 + tx * 8 + j;
            float v = acc[i][j] + bias[n];
            if (mode == 0) {
                dst[(size_t)m * HID + n] = v;
            } else {
                int b = m >> 11, s = m & 2047;
                int h = n >> 6, d = n & 63;
                if (mode == 1)
                    dst[(((size_t)(b * NUM_HEADS + h) * SEQ + s) * 128) + off + d] = v;
                else
                    dst[(((size_t)(b * NUM_HEADS + h) * SEQ + s) * 64) + d] = v;
            }
        }
    }
}

// KPK[...,0:64] = K (stored at 64:) + P (stored in QP at 64:)
__global__ __launch_bounds__(256) void kp_add()
{
    size_t i = (size_t)blockIdx.x * 256 + threadIdx.x;  // over BH*SEQ*64
    size_t r = i >> 6, d = i & 63;
    g_KPK[r * 128 + d] = g_KPK[r * 128 + 64 + d] + g_QP[r * 128 + 64 + d];
}

// ---------------------------------------------------------------------------
// Scores: per (b,h), S[q,k] = (QP[q,:] . KPK[k,:]) * SCALE + mask[q,k]
// 2048x2048, K=128. Same 128x128x16 tiling. Writes raw (pre-softmax) scores.
// ---------------------------------------------------------------------------
__global__ __launch_bounds__(256) void gemm_scores(
    const float* __restrict__ mask, float* __restrict__ weights)
{
    const int bh = blockIdx.z;
    const float* A = g_QP  + (size_t)bh * SEQ * 128;
    const float* B = g_KPK + (size_t)bh * SEQ * 128;
    float* C = weights + (size_t)bh * SEQ * SEQ;

    __shared__ float As[16][128];
    __shared__ float Bs[16][128];
    const int tid = threadIdx.x;
    const int tx = tid & 15, ty = tid >> 4;
    const int m0 = blockIdx.y * 128, n0 = blockIdx.x * 128;

    float acc[8][8];
#pragma unroll
    for (int i = 0; i < 8; i++)
#pragma unroll
        for (int j = 0; j < 8; j++) acc[i][j] = 0.f;

    for (int kt = 0; kt < 128; kt += 16) {
#pragma unroll
        for (int l = 0; l < 2; l++) {
            int lin = tid + l * 256;
            int row = lin >> 2, c4 = lin & 3;
            float4 a = *(const float4*)(A + (size_t)(m0 + row) * 128 + kt + c4 * 4);
            As[c4 * 4 + 0][row] = a.x; As[c4 * 4 + 1][row] = a.y;
            As[c4 * 4 + 2][row] = a.z; As[c4 * 4 + 3][row] = a.w;
            float4 b = *(const float4*)(B + (size_t)(n0 + row) * 128 + kt + c4 * 4);
            Bs[c4 * 4 + 0][row] = b.x; Bs[c4 * 4 + 1][row] = b.y;
            Bs[c4 * 4 + 2][row] = b.z; Bs[c4 * 4 + 3][row] = b.w;
        }
        __syncthreads();
#pragma unroll
        for (int k = 0; k < 16; k++) {
            float a[8], b[8];
#pragma unroll
            for (int i = 0; i < 8; i++) a[i] = As[k][ty * 8 + i];
#pragma unroll
            for (int j = 0; j < 8; j++) b[j] = Bs[k][tx * 8 + j];
#pragma unroll
            for (int i = 0; i < 8; i++)
#pragma unroll
                for (int j = 0; j < 8; j++) acc[i][j] += a[i] * b[j];
        }
        __syncthreads();
    }

#pragma unroll
    for (int i = 0; i < 8; i++) {
        int q = m0 + ty * 8 + i;
#pragma unroll
        for (int j = 0; j < 8; j++) {
            int k = n0 + tx * 8 + j;
            C[(size_t)q * SEQ + k] = acc[i][j] * SCALE + mask[(size_t)q * SEQ + k];
        }
    }
}

// In-place row softmax over 2048 cols. One block (256 thr) per row.
__global__ __launch_bounds__(256) void softmax_rows(float* __restrict__ w)
{
    __shared__ float red[256];
    const size_t row = blockIdx.x;
    float* p = w + row * (size_t)SEQ;
    const int tid = threadIdx.x;

    float v[8];
    float mx = -1e30f;
#pragma unroll
    for (int i = 0; i < 8; i++) {
        v[i] = p[tid + i * 256];
        mx = fmaxf(mx, v[i]);
    }
    red[tid] = mx;
    __syncthreads();
    for (int s = 128; s > 0; s >>= 1) {
        if (tid < s) red[tid] = fmaxf(red[tid], red[tid + s]);
        __syncthreads();
    }
    mx = red[0];
    __syncthreads();

    float sum = 0.f;
#pragma unroll
    for (int i = 0; i < 8; i++) {
        v[i] = __expf(v[i] - mx);
        sum += v[i];
    }
    red[tid] = sum;
    __syncthreads();
    for (int s = 128; s > 0; s >>= 1) {
        if (tid < s) red[tid] += red[tid + s];
        __syncthreads();
    }
    float inv = 1.f / red[0];
#pragma unroll
    for (int i = 0; i < 8; i++) p[tid + i * 256] = v[i] * inv;
}

// ---------------------------------------------------------------------------
// AV: per (b,h), O[q,d] = sum_k W[q,k]*V[k,d].  M=2048, N=64, K=2048.
// BM=128, BN=64, BK=32. 256 threads, 8x4 per thread. O stored [b,s,h*64+d].
// ---------------------------------------------------------------------------
__global__ __launch_bounds__(256) void gemm_av(const float* __restrict__ weights)
{
    const int bh = blockIdx.y;
    const int b = bh >> 4, h = bh & 15;
    const float* Wm = weights + (size_t)bh * SEQ * SEQ;
    const float* V  = g_V + (size_t)bh * SEQ * HDIM;

    __shared__ float Ws[32][128];
    __shared__ float Vs[32][64];
    const int tid = threadIdx.x;
    const int tx = tid & 15, ty = tid >> 4;
    const int m0 = blockIdx.x * 128;

    float acc[8][4];
#pragma unroll
    for (int i = 0; i < 8; i++)
#pragma unroll
        for (int j = 0; j < 4; j++) acc[i][j] = 0.f;

    for (int kt = 0; kt < SEQ; kt += 32) {
#pragma unroll
        for (int l = 0; l < 4; l++) {
            int lin = tid + l * 256;             // [0,1024)
            int row = lin >> 3, c4 = lin & 7;
            float4 a = *(const float4*)(Wm + (size_t)(m0 + row) * SEQ + kt + c4 * 4);
            Ws[c4 * 4 + 0][row] = a.x; Ws[c4 * 4 + 1][row] = a.y;
            Ws[c4 * 4 + 2][row] = a.z; Ws[c4 * 4 + 3][row] = a.w;
        }
#pragma unroll
        for (int l = 0; l < 2; l++) {
            int lin = tid + l * 256;             // [0,512)
            int row = lin >> 4, c4 = lin & 15;
            *(float4*)&Vs[row][c4 * 4] =
                *(const float4*)(V + (size_t)(kt + row) * HDIM + c4 * 4);
        }
        __syncthreads();
#pragma unroll
        for (int k = 0; k < 32; k++) {
            float a[8], bb[4];
#pragma unroll
            for (int i = 0; i < 8; i++) a[i] = Ws[k][ty * 8 + i];
#pragma unroll
            for (int j = 0; j < 4; j++) bb[j] = Vs[k][tx * 4 + j];
#pragma unroll
            for (int i = 0; i < 8; i++)
#pragma unroll
                for (int j = 0; j < 4; j++) acc[i][j] += a[i] * bb[j];
        }
        __syncthreads();
    }

#pragma unroll
    for (int i = 0; i < 8; i++) {
        int s = m0 + ty * 8 + i;
#pragma unroll
        for (int j = 0; j < 4; j++) {
            int d = tx * 4 + j;
            g_O[(size_t)b * SEQ * HID + (size_t)s * HID + h * 64 + d] = acc[i][j];
        }
    }
}

// ---------------------------------------------------------------------------
extern "C" void kernel_launch(void* const* d_in, const int* in_sizes, int n_in,
                              void* d_out, int out_size)
{
    const float* q    = (const float*)d_in[0];
    const float* k    = (const float*)d_in[1];
    const float* v    = (const float*)d_in[2];
    const float* pos  = (const float*)d_in[3];
    const float* mask = (const float*)d_in[4];
    const float* Wq = (const float*)d_in[5];  const float* bq = (const float*)d_in[6];
    const float* Wk = (const float*)d_in[7];  const float* bk = (const float*)d_in[8];
    const float* Wv = (const float*)d_in[9];  const float* bv = (const float*)d_in[10];
    const float* Wp = (const float*)d_in[11]; const float* bp = (const float*)d_in[12];
    const float* Wo = (const float*)d_in[13]; const float* bo = (const float*)d_in[14];

    float* out = (float*)d_out;
    float* weights = out + (size_t)BATCH * SEQ * HID;   // out first, then weights

    float *QP, *KPK, *Vd, *O;
    cudaGetSymbolAddress((void**)&QP,  g_QP);
    cudaGetSymbolAddress((void**)&KPK, g_KPK);
    cudaGetSymbolAddress((void**)&Vd,  g_V);
    cudaGetSymbolAddress((void**)&O,   g_O);

    dim3 blk(256);
    dim3 gproj(HID / 128, M_TOTAL / 128);   // (8, 32)

    gemm_proj<<<gproj, blk>>>(q,   Wq, bq, QP,  1, 0);   // Q  -> QP[:,0:64]
    gemm_proj<<<gproj, blk>>>(pos, Wp, bp, QP,  1, 64);  // P  -> QP[:,64:128]
    gemm_proj<<<gproj, blk>>>(k,   Wk, bk, KPK, 1, 64);  // K  -> KPK[:,64:128]
    gemm_proj<<<gproj, blk>>>(v,   Wv, bv, Vd,  2, 0);   // V

    kp_add<<<(BH * SEQ * 64) / 256, blk>>>();            // KPK[:,0:64] = K + P

    dim3 gsc(SEQ / 128, SEQ / 128, BH);                  // (16,16,32)
    gemm_scores<<<gsc, blk>>>(mask, weights);

    softmax_rows<<<BH * SEQ, blk>>>(weights);

    gemm_av<<<dim3(SEQ / 128, BH), blk>>>(weights);

    gemm_proj<<<gproj, blk>>>(O, Wo, bo, out, 0, 0);     // final projection
}

// round 5
// speedup vs baseline: 1.0028x; 1.0019x over previous
#include <cuda_runtime.h>
#include <cstdint>

#define NUM_HEADS 16
#define SEQ 2048
#define HDIM 64
#define HID 1024
#define BATCH 2
#define M_TOTAL (BATCH * SEQ)      // 4096
#define BH (BATCH * NUM_HEADS)     // 32
#define SCALE 0.125f               // 1/sqrt(64)

// Scratch (no cudaMalloc allowed): 96 MB total
__device__ float g_QP [(size_t)BH * SEQ * 128];   // [b,h,s, 0:64]=Q, [64:128]=P
__device__ float g_KPK[(size_t)BH * SEQ * 128];   // [b,h,s, 0:64]=K+P, [64:128]=K
__device__ float g_V  [(size_t)BH * SEQ * HDIM];  // [b,h,s,d]
__device__ float g_O  [(size_t)M_TOTAL * HID];    // [b,s,h*64+d]

// ---------------------------------------------------------------------------
// NT GEMM with bias: C[m,n] = sum_k X[m,k]*W[n,k] + bias[n]
// M=4096, N=1024, K=1024. BM=BN=128, BK=16. 256 threads, 8x8 per thread.
// mode 0: dst[m*HID + n]                          (final output)
// mode 1: dst[((b*16+h)*SEQ+s)*128 + off + d]     (QP / KPK head layout)
// mode 2: dst[((b*16+h)*SEQ+s)*64 + d]            (V head layout)
// ---------------------------------------------------------------------------
__global__ __launch_bounds__(256) void gemm_proj(
    const float* __restrict__ X, const float* __restrict__ W,
    const float* __restrict__ bias, float* __restrict__ dst,
    int mode, int off)
{
    __shared__ float As[16][128];
    __shared__ float Bs[16][128];
    const int tid = threadIdx.x;
    const int tx = tid & 15, ty = tid >> 4;
    const int m0 = blockIdx.y * 128, n0 = blockIdx.x * 128;

    float acc[8][8];
#pragma unroll
    for (int i = 0; i < 8; i++)
#pragma unroll
        for (int j = 0; j < 8; j++) acc[i][j] = 0.f;

    for (int kt = 0; kt < 1024; kt += 16) {
#pragma unroll
        for (int l = 0; l < 2; l++) {
            int lin = tid + l * 256;             // [0,512)
            int row = lin >> 2, c4 = lin & 3;
            float4 a = *(const float4*)(X + (size_t)(m0 + row) * 1024 + kt + c4 * 4);
            As[c4 * 4 + 0][row] = a.x; As[c4 * 4 + 1][row] = a.y;
            As[c4 * 4 + 2][row] = a.z; As[c4 * 4 + 3][row] = a.w;
            float4 b = *(const float4*)(W + (size_t)(n0 + row) * 1024 + kt + c4 * 4);
            Bs[c4 * 4 + 0][row] = b.x; Bs[c4 * 4 + 1][row] = b.y;
            Bs[c4 * 4 + 2][row] = b.z; Bs[c4 * 4 + 3][row] = b.w;
        }
        __syncthreads();
#pragma unroll
        for (int k = 0; k < 16; k++) {
            float a[8], b[8];
#pragma unroll
            for (int i = 0; i < 8; i++) a[i] = As[k][ty * 8 + i];
#pragma unroll
            for (int j = 0; j < 8; j++) b[j] = Bs[k][tx * 8 + j];
#pragma unroll
            for (int i = 0; i < 8; i++)
#pragma unroll
                for (int j = 0; j < 8; j++) acc[i][j] += a[i] * b[j];
        }
        __syncthreads();
    }

#pragma unroll
    for (int i = 0; i < 8; i++) {
        int m = m0 + ty * 8 + i;
#pragma unroll
        for (int j = 0; j < 8; j++) {
            int n = n0 + tx * 8 + j;
            float v = acc[i][j] + bias[n];
            if (mode == 0) {
                dst[(size_t)m * HID + n] = v;
            } else {
                int b = m >> 11, s = m & 2047;
                int h = n >> 6, d = n & 63;
                if (mode == 1)
                    dst[(((size_t)(b * NUM_HEADS + h) * SEQ + s) * 128) + off + d] = v;
                else
                    dst[(((size_t)(b * NUM_HEADS + h) * SEQ + s) * 64) + d] = v;
            }
        }
    }
}

// KPK[...,0:64] = K (stored at 64:) + P (stored in QP at 64:)
__global__ __launch_bounds__(256) void kp_add()
{
    size_t i = (size_t)blockIdx.x * 256 + threadIdx.x;  // over BH*SEQ*64
    size_t r = i >> 6, d = i & 63;
    g_KPK[r * 128 + d] = g_KPK[r * 128 + 64 + d] + g_QP[r * 128 + 64 + d];
}

// ---------------------------------------------------------------------------
// Scores: per (b,h), S[q,k] = (QP[q,:] . KPK[k,:]) * SCALE + mask[q,k]
// 2048x2048, K=128. Same 128x128x16 tiling. Writes raw (pre-softmax) scores.
// ---------------------------------------------------------------------------
__global__ __launch_bounds__(256) void gemm_scores(
    const float* __restrict__ mask, float* __restrict__ weights)
{
    const int bh = blockIdx.z;
    const float* A = g_QP  + (size_t)bh * SEQ * 128;
    const float* B = g_KPK + (size_t)bh * SEQ * 128;
    float* C = weights + (size_t)bh * SEQ * SEQ;

    __shared__ float As[16][128];
    __shared__ float Bs[16][128];
    const int tid = threadIdx.x;
    const int tx = tid & 15, ty = tid >> 4;
    const int m0 = blockIdx.y * 128, n0 = blockIdx.x * 128;

    float acc[8][8];
#pragma unroll
    for (int i = 0; i < 8; i++)
#pragma unroll
        for (int j = 0; j < 8; j++) acc[i][j] = 0.f;

    for (int kt = 0; kt < 128; kt += 16) {
#pragma unroll
        for (int l = 0; l < 2; l++) {
            int lin = tid + l * 256;
            int row = lin >> 2, c4 = lin & 3;
            float4 a = *(const float4*)(A + (size_t)(m0 + row) * 128 + kt + c4 * 4);
            As[c4 * 4 + 0][row] = a.x; As[c4 * 4 + 1][row] = a.y;
            As[c4 * 4 + 2][row] = a.z; As[c4 * 4 + 3][row] = a.w;
            float4 b = *(const float4*)(B + (size_t)(n0 + row) * 128 + kt + c4 * 4);
            Bs[c4 * 4 + 0][row] = b.x; Bs[c4 * 4 + 1][row] = b.y;
            Bs[c4 * 4 + 2][row] = b.z; Bs[c4 * 4 + 3][row] = b.w;
        }
        __syncthreads();
#pragma unroll
        for (int k = 0; k < 16; k++) {
            float a[8], b[8];
#pragma unroll
            for (int i = 0; i < 8; i++) a[i] = As[k][ty * 8 + i];
#pragma unroll
            for (int j = 0; j < 8; j++) b[j] = Bs[k][tx * 8 + j];
#pragma unroll
            for (int i = 0; i < 8; i++)
#pragma unroll
                for (int j = 0; j < 8; j++) acc[i][j] += a[i] * b[j];
        }
        __syncthreads();
    }

#pragma unroll
    for (int i = 0; i < 8; i++) {
        int q = m0 + ty * 8 + i;
#pragma unroll
        for (int j = 0; j < 8; j++) {
            int k = n0 + tx * 8 + j;
            C[(size_t)q * SEQ + k] = acc[i][j] * SCALE + mask[(size_t)q * SEQ + k];
        }
    }
}

// In-place row softmax over 2048 cols. One block (256 thr) per row.
__global__ __launch_bounds__(256) void softmax_rows(float* __restrict__ w)
{
    __shared__ float red[256];
    const size_t row = blockIdx.x;
    float* p = w + row * (size_t)SEQ;
    const int tid = threadIdx.x;

    float v[8];
    float mx = -1e30f;
#pragma unroll
    for (int i = 0; i < 8; i++) {
        v[i] = p[tid + i * 256];
        mx = fmaxf(mx, v[i]);
    }
    red[tid] = mx;
    __syncthreads();
    for (int s = 128; s > 0; s >>= 1) {
        if (tid < s) red[tid] = fmaxf(red[tid], red[tid + s]);
        __syncthreads();
    }
    mx = red[0];
    __syncthreads();

    float sum = 0.f;
#pragma unroll
    for (int i = 0; i < 8; i++) {
        v[i] = __expf(v[i] - mx);
        sum += v[i];
    }
    red[tid] = sum;
    __syncthreads();
    for (int s = 128; s > 0; s >>= 1) {
        if (tid < s) red[tid] += red[tid + s];
        __syncthreads();
    }
    float inv = 1.f / red[0];
#pragma unroll
    for (int i = 0; i < 8; i++) p[tid + i * 256] = v[i] * inv;
}

// ---------------------------------------------------------------------------
// AV: per (b,h), O[q,d] = sum_k W[q,k]*V[k,d].  M=2048, N=64, K=2048.
// BM=128, BN=64, BK=32. 256 threads, 8x4 per thread. O stored [b,s,h*64+d].
// ---------------------------------------------------------------------------
__global__ __launch_bounds__(256) void gemm_av(const float* __restrict__ weights)
{
    const int bh = blockIdx.y;
    const int b = bh >> 4, h = bh & 15;
    const float* Wm = weights + (size_t)bh * SEQ * SEQ;
    const float* V  = g_V + (size_t)bh * SEQ * HDIM;

    __shared__ float Ws[32][128];
    __shared__ float Vs[32][64];
    const int tid = threadIdx.x;
    const int tx = tid & 15, ty = tid >> 4;
    const int m0 = blockIdx.x * 128;

    float acc[8][4];
#pragma unroll
    for (int i = 0; i < 8; i++)
#pragma unroll
        for (int j = 0; j < 4; j++) acc[i][j] = 0.f;

    for (int kt = 0; kt < SEQ; kt += 32) {
#pragma unroll
        for (int l = 0; l < 4; l++) {
            int lin = tid + l * 256;             // [0,1024)
            int row = lin >> 3, c4 = lin & 7;
            float4 a = *(const float4*)(Wm + (size_t)(m0 + row) * SEQ + kt + c4 * 4);
            Ws[c4 * 4 + 0][row] = a.x; Ws[c4 * 4 + 1][row] = a.y;
            Ws[c4 * 4 + 2][row] = a.z; Ws[c4 * 4 + 3][row] = a.w;
        }
#pragma unroll
        for (int l = 0; l < 2; l++) {
            int lin = tid + l * 256;             // [0,512)
            int row = lin >> 4, c4 = lin & 15;
            *(float4*)&Vs[row][c4 * 4] =
                *(const float4*)(V + (size_t)(kt + row) * HDIM + c4 * 4);
        }
        __syncthreads();
#pragma unroll
        for (int k = 0; k < 32; k++) {
            float a[8], bb[4];
#pragma unroll
            for (int i = 0; i < 8; i++) a[i] = Ws[k][ty * 8 + i];
#pragma unroll
            for (int j = 0; j < 4; j++) bb[j] = Vs[k][tx * 4 + j];
#pragma unroll
            for (int i = 0; i < 8; i++)
#pragma unroll
                for (int j = 0; j < 4; j++) acc[i][j] += a[i] * bb[j];
        }
        __syncthreads();
    }

#pragma unroll
    for (int i = 0; i < 8; i++) {
        int s = m0 + ty * 8 + i;
#pragma unroll
        for (int j = 0; j < 4; j++) {
            int d = tx * 4 + j;
            g_O[(size_t)b * SEQ * HID + (size_t)s * HID + h * 64 + d] = acc[i][j];
        }
    }
}

// ---------------------------------------------------------------------------
extern "C" void kernel_launch(void* const* d_in, const int* in_sizes, int n_in,
                              void* d_out, int out_size)
{
    const float* q    = (const float*)d_in[0];
    const float* k    = (const float*)d_in[1];
    const float* v    = (const float*)d_in[2];
    const float* pos  = (const float*)d_in[3];
    const float* mask = (const float*)d_in[4];
    const float* Wq = (const float*)d_in[5];  const float* bq = (const float*)d_in[6];
    const float* Wk = (const float*)d_in[7];  const float* bk = (const float*)d_in[8];
    const float* Wv = (const float*)d_in[9];  const float* bv = (const float*)d_in[10];
    const float* Wp = (const float*)d_in[11]; const float* bp = (const float*)d_in[12];
    const float* Wo = (const float*)d_in[13]; const float* bo = (const float*)d_in[14];

    float* out = (float*)d_out;
    float* weights = out + (size_t)BATCH * SEQ * HID;   // out first, then weights

    float *QP, *KPK, *Vd, *O;
    cudaGetSymbolAddress((void**)&QP,  g_QP);
    cudaGetSymbolAddress((void**)&KPK, g_KPK);
    cudaGetSymbolAddress((void**)&Vd,  g_V);
    cudaGetSymbolAddress((void**)&O,   g_O);

    dim3 blk(256);
    dim3 gproj(HID / 128, M_TOTAL / 128);   // (8, 32)

    gemm_proj<<<gproj, blk>>>(q,   Wq, bq, QP,  1, 0);   // Q  -> QP[:,0:64]
    gemm_proj<<<gproj, blk>>>(pos, Wp, bp, QP,  1, 64);  // P  -> QP[:,64:128]
    gemm_proj<<<gproj, blk>>>(k,   Wk, bk, KPK, 1, 64);  // K  -> KPK[:,64:128]
    gemm_proj<<<gproj, blk>>>(v,   Wv, bv, Vd,  2, 0);   // V

    kp_add<<<(BH * SEQ * 64) / 256, blk>>>();            // KPK[:,0:64] = K + P

    dim3 gsc(SEQ / 128, SEQ / 128, BH);                  // (16,16,32)
    gemm_scores<<<gsc, blk>>>(mask, weights);

    softmax_rows<<<BH * SEQ, blk>>>(weights);

    gemm_av<<<dim3(SEQ / 128, BH), blk>>>(weights);

    gemm_proj<<<gproj, blk>>>(O, Wo, bo, out, 0, 0);     // final projection
}

// round 7
// speedup vs baseline: 2.3794x; 2.3726x over previous
#include <cuda_runtime.h>
#include <cuda_bf16.h>
#include <cstdint>

#define NUM_HEADS 16
#define SEQ 2048
#define HID 1024
#define BATCH 2
#define M_TOTAL 4096
#define BH 32
#define SCALEF 0.125f

// Scratch (no cudaMalloc allowed)
__device__ float g_QP [(size_t)BH * SEQ * 128];   // [bh][s][0:64]=Q, [64:128]=P
__device__ float g_KPK[(size_t)BH * SEQ * 128];   // [bh][s][0:64]=K+P, [64:128]=K
__device__ float g_V  [(size_t)BH * SEQ * 64];    // [bh][s][d]
__device__ float g_O  [(size_t)M_TOTAL * HID];    // [b,s,h*64+d]

// ============================ PTX helpers ==================================
__device__ __forceinline__ uint32_t smem_u32(const void* p) {
    uint32_t a;
    asm("{ .reg .u64 t; cvta.to.shared.u64 t, %1; cvt.u32.u64 %0, t; }"
        : "=r"(a) : "l"(p));
    return a;
}

__device__ __forceinline__ void ldsm4(uint32_t& r0, uint32_t& r1,
                                      uint32_t& r2, uint32_t& r3, uint32_t addr) {
    asm volatile("ldmatrix.sync.aligned.m8n8.x4.shared.b16 {%0,%1,%2,%3}, [%4];"
                 : "=r"(r0), "=r"(r1), "=r"(r2), "=r"(r3) : "r"(addr));
}

__device__ __forceinline__ void mma16816(float* d, const uint32_t* a, const uint32_t* b) {
    asm volatile(
        "mma.sync.aligned.m16n8k16.row.col.f32.bf16.bf16.f32 "
        "{%0,%1,%2,%3},{%4,%5,%6,%7},{%8,%9},{%0,%1,%2,%3};"
        : "+f"(d[0]), "+f"(d[1]), "+f"(d[2]), "+f"(d[3])
        : "r"(a[0]), "r"(a[1]), "r"(a[2]), "r"(a[3]), "r"(b[0]), "r"(b[1]));
}

// Swizzled byte offset inside a tile of 64B rows (32 bf16 per row):
// chunk (16B) index c in [0,4), XORed with (row>>1)&3.
__device__ __forceinline__ uint32_t swz(int row, int kchunk) {
    return (uint32_t)(row * 64 + ((kchunk ^ ((row >> 1) & 3)) << 4));
}

// ====================== stage loaders (fp32 -> bf16 hi/lo) =================
template<int ROWS>
__device__ __forceinline__ void ldg_rows(const float* __restrict__ src, int ld,
                                         int kt, float4* reg, int tid) {
#pragma unroll
    for (int it = 0; it < ROWS * 8 / 256; it++) {
        int i = tid + it * 256;
        int r = i >> 3, c4 = i & 7;
        reg[it] = *(const float4*)(src + (size_t)r * ld + kt + c4 * 4);
    }
}

template<int ROWS>
__device__ __forceinline__ void sts_rows(char* hi, char* lo,
                                         const float4* reg, int tid) {
#pragma unroll
    for (int it = 0; it < ROWS * 8 / 256; it++) {
        int i = tid + it * 256;
        int r = i >> 3, c4 = i & 7;
        float4 v = reg[it];
        __nv_bfloat162 h01 = __float22bfloat162_rn(make_float2(v.x, v.y));
        __nv_bfloat162 h23 = __float22bfloat162_rn(make_float2(v.z, v.w));
        float2 f01 = __bfloat1622float2(h01);
        float2 f23 = __bfloat1622float2(h23);
        __nv_bfloat162 l01 = __float22bfloat162_rn(make_float2(v.x - f01.x, v.y - f01.y));
        __nv_bfloat162 l23 = __float22bfloat162_rn(make_float2(v.z - f23.x, v.w - f23.y));
        uint32_t off = swz(r, c4 >> 1) + ((c4 & 1) << 3);
        *(uint2*)(hi + off) = make_uint2(*(uint32_t*)&h01, *(uint32_t*)&h23);
        *(uint2*)(lo + off) = make_uint2(*(uint32_t*)&l01, *(uint32_t*)&l23);
    }
}

// Transposed loader for AV's V: source V[k][d] (d contiguous, ld=64),
// builds B tile [64 d-rows][32 k] bf16 hi/lo.
__device__ __forceinline__ void ldg_T64(const float* __restrict__ src, int kt,
                                        float4* reg, int tid) {
#pragma unroll
    for (int it = 0; it < 2; it++) {
        int i = tid + it * 256;
        int kr = i >> 4, c4 = i & 15;
        reg[it] = *(const float4*)(src + (size_t)(kt + kr) * 64 + c4 * 4);
    }
}

__device__ __forceinline__ void sts_T64(char* hi, char* lo,
                                        const float4* reg, int tid) {
#pragma unroll
    for (int it = 0; it < 2; it++) {
        int i = tid + it * 256;
        int kr = i >> 4, c4 = i & 15;
        float4 v = reg[it];
        float xs[4] = {v.x, v.y, v.z, v.w};
#pragma unroll
        for (int e = 0; e < 4; e++) {
            int d = c4 * 4 + e;
            __nv_bfloat16 h = __float2bfloat16(xs[e]);
            __nv_bfloat16 l = __float2bfloat16(xs[e] - __bfloat162float(h));
            uint32_t off = swz(d, kr >> 3) + ((kr & 7) << 1);
            *(__nv_bfloat16*)(hi + off) = h;
            *(__nv_bfloat16*)(lo + off) = l;
        }
    }
}

// ====================== generic HMMA NT GEMM (bf16x3) ======================
// C[m,n] = sum_k A[m,k]*B[n,k]; fp32 inputs split into bf16 hi/lo, 3 MMAs.
// CTA tile 128 x BN, BK=32, double-buffered SMEM, 256 threads (8 warps).
// EPI: 0 out(+bias); 1 QP/KPK scatter(+bias); 2 V scatter(+bias);
//      3 scores (scale+mask); 4 AV -> g_O layout
template<int BN, int EPI, bool BTRANS>
__global__ __launch_bounds__(256)
void mma_gemm(const float* __restrict__ Asrc, const float* __restrict__ Bsrc,
              const float* __restrict__ aux, float* __restrict__ dst,
              int K, int lda, int ldb,
              long long a_bh, long long b_bh, int eoff)
{
    extern __shared__ char smem[];
    constexpr int ATB = 128 * 64;              // A tile bytes (bf16, one copy)
    constexpr int BTB = BN * 64;
    constexpr int STG = 2 * ATB + 2 * BTB;     // hi+lo for A and B
    constexpr int WARPS_M = (BN == 128) ? 2 : 4;
    constexpr int WM = 128 / WARPS_M;          // 64 or 32
    constexpr int WN = BN / (8 / WARPS_M);     // 32
    constexpr int MT = WM / 16;                // 4 or 2
    constexpr int NT = WN / 8;                 // 4
    constexpr int NB = BTRANS ? 2 : BN * 8 / 256;

    const int tid = threadIdx.x, wid = tid >> 5, lane = tid & 31;
    const int g = lane >> 2, tig = lane & 3;
    const int wm = wid % WARPS_M, wn = wid / WARPS_M;
    const int m0 = blockIdx.y * 128, n0 = blockIdx.x * BN, bh = blockIdx.z;

    const float* A = Asrc + (size_t)bh * a_bh + (size_t)m0 * lda;
    const float* B = Bsrc + (size_t)bh * b_bh + (BTRANS ? 0 : (size_t)n0 * ldb);
    const uint32_t sb = smem_u32(smem);

    float acc[MT][NT][4];
#pragma unroll
    for (int i = 0; i < MT; i++)
#pragma unroll
        for (int j = 0; j < NT; j++)
#pragma unroll
            for (int e = 0; e < 4; e++) acc[i][j][e] = 0.f;

    const int nch = K >> 5;
    float4 ra[4], rb[NB];

    // preload stage 0
    ldg_rows<128>(A, lda, 0, ra, tid);
    if (BTRANS) ldg_T64(B, 0, rb, tid);
    else        ldg_rows<BN>(B, ldb, 0, rb, tid);
    sts_rows<128>(smem, smem + ATB, ra, tid);
    if (BTRANS) sts_T64(smem + 2 * ATB, smem + 2 * ATB + BTB, rb, tid);
    else        sts_rows<BN>(smem + 2 * ATB, smem + 2 * ATB + BTB, rb, tid);
    __syncthreads();

    for (int c = 0; c < nch; c++) {
        const int buf = c & 1;
        const uint32_t sA = sb + buf * STG;
        const uint32_t sB = sA + 2 * ATB;

        // issue next-stage global loads early (held in registers)
        if (c + 1 < nch) {
            const int kt = (c + 1) * 32;
            ldg_rows<128>(A, lda, kt, ra, tid);
            if (BTRANS) ldg_T64(B, kt, rb, tid);
            else        ldg_rows<BN>(B, ldb, kt, rb, tid);
        }

#pragma unroll
        for (int ks = 0; ks < 2; ks++) {
            const int k0 = ks * 16;
            uint32_t ah[MT][4], al[MT][4], bhf[NT][2], blf[NT][2];

            // A fragments (hi and lo)
#pragma unroll
            for (int mt = 0; mt < MT; mt++) {
                const int sub = lane >> 3;
                const int row = wm * WM + mt * 16 + (lane & 7) + ((sub & 1) << 3);
                const int kk = k0 + ((sub >> 1) << 3);
                const uint32_t addr = sA + swz(row, kk >> 3);
                ldsm4(ah[mt][0], ah[mt][1], ah[mt][2], ah[mt][3], addr);
                ldsm4(al[mt][0], al[mt][1], al[mt][2], al[mt][3], addr + ATB);
            }
            // B fragments: one x4 covers two n8 tiles
#pragma unroll
            for (int np = 0; np < NT / 2; np++) {
                const int sub = lane >> 3;
                const int row = wn * WN + np * 16 + (lane & 7) + ((sub >> 1) << 3);
                const int kk = k0 + ((sub & 1) << 3);
                const uint32_t addr = sB + swz(row, kk >> 3);
                uint32_t r0, r1, r2, r3;
                ldsm4(r0, r1, r2, r3, addr);
                bhf[np * 2][0] = r0; bhf[np * 2][1] = r1;
                bhf[np * 2 + 1][0] = r2; bhf[np * 2 + 1][1] = r3;
                ldsm4(r0, r1, r2, r3, addr + BTB);
                blf[np * 2][0] = r0; blf[np * 2][1] = r1;
                blf[np * 2 + 1][0] = r2; blf[np * 2 + 1][1] = r3;
            }
            // 3-term split MMAs
#pragma unroll
            for (int mt = 0; mt < MT; mt++)
#pragma unroll
                for (int nt = 0; nt < NT; nt++) {
                    mma16816(acc[mt][nt], ah[mt], bhf[nt]);
                    mma16816(acc[mt][nt], ah[mt], blf[nt]);
                    mma16816(acc[mt][nt], al[mt], bhf[nt]);
                }
        }

        if (c + 1 < nch) {
            __syncthreads();
            char* nbuf = smem + (buf ^ 1) * STG;
            sts_rows<128>(nbuf, nbuf + ATB, ra, tid);
            if (BTRANS) sts_T64(nbuf + 2 * ATB, nbuf + 2 * ATB + BTB, rb, tid);
            else        sts_rows<BN>(nbuf + 2 * ATB, nbuf + 2 * ATB + BTB, rb, tid);
            __syncthreads();
        }
    }

    // ------------------------------ epilogue -------------------------------
#pragma unroll
    for (int mt = 0; mt < MT; mt++) {
#pragma unroll
        for (int nt = 0; nt < NT; nt++) {
            const int ncol = n0 + wn * WN + nt * 8 + tig * 2;
#pragma unroll
            for (int half = 0; half < 2; half++) {
                const int m = m0 + wm * WM + mt * 16 + g + half * 8;
                float v0 = acc[mt][nt][half * 2 + 0];
                float v1 = acc[mt][nt][half * 2 + 1];
                if (EPI == 0) {
                    v0 += aux[ncol]; v1 += aux[ncol + 1];
                    *(float2*)(dst + (size_t)m * HID + ncol) = make_float2(v0, v1);
                } else if (EPI == 1) {
                    v0 += aux[ncol]; v1 += aux[ncol + 1];
                    int b = m >> 11, s = m & 2047, h = ncol >> 6, d = ncol & 63;
                    *(float2*)(dst + (((size_t)(b * NUM_HEADS + h) * SEQ + s) * 128)
                               + eoff + d) = make_float2(v0, v1);
                } else if (EPI == 2) {
                    v0 += aux[ncol]; v1 += aux[ncol + 1];
                    int b = m >> 11, s = m & 2047, h = ncol >> 6, d = ncol & 63;
                    *(float2*)(dst + (((size_t)(b * NUM_HEADS + h) * SEQ + s) * 64)
                               + d) = make_float2(v0, v1);
                } else if (EPI == 3) {
                    const float* mrow = aux + (size_t)m * SEQ + ncol;
                    *(float2*)(dst + (size_t)bh * SEQ * SEQ + (size_t)m * SEQ + ncol) =
                        make_float2(v0 * SCALEF + mrow[0], v1 * SCALEF + mrow[1]);
                } else {  // EPI == 4
                    int b = bh >> 4, h = bh & 15;
                    *(float2*)(dst + ((size_t)b * SEQ + m) * HID + h * 64 + ncol) =
                        make_float2(v0, v1);
                }
            }
        }
    }
}

// ====================== small elementwise / softmax ========================
__global__ __launch_bounds__(256) void kp_add()
{
    size_t i = (size_t)blockIdx.x * 256 + threadIdx.x;  // over BH*SEQ*64
    size_t r = i >> 6, d = i & 63;
    g_KPK[r * 128 + d] = g_KPK[r * 128 + 64 + d] + g_QP[r * 128 + 64 + d];
}

__global__ __launch_bounds__(256) void softmax_rows(float* __restrict__ w)
{
    __shared__ float red[256];
    const size_t row = blockIdx.x;
    float* p = w + row * (size_t)SEQ;
    const int tid = threadIdx.x;

    float v[8];
    float mx = -1e30f;
#pragma unroll
    for (int i = 0; i < 8; i++) {
        v[i] = p[tid + i * 256];
        mx = fmaxf(mx, v[i]);
    }
    red[tid] = mx;
    __syncthreads();
    for (int s = 128; s > 0; s >>= 1) {
        if (tid < s) red[tid] = fmaxf(red[tid], red[tid + s]);
        __syncthreads();
    }
    mx = red[0];
    __syncthreads();

    float sum = 0.f;
#pragma unroll
    for (int i = 0; i < 8; i++) {
        v[i] = __expf(v[i] - mx);
        sum += v[i];
    }
    red[tid] = sum;
    __syncthreads();
    for (int s = 128; s > 0; s >>= 1) {
        if (tid < s) red[tid] += red[tid + s];
        __syncthreads();
    }
    float inv = 1.f / red[0];
#pragma unroll
    for (int i = 0; i < 8; i++) p[tid + i * 256] = v[i] * inv;
}

// ===========================================================================
extern "C" void kernel_launch(void* const* d_in, const int* in_sizes, int n_in,
                              void* d_out, int out_size)
{
    const float* q    = (const float*)d_in[0];
    const float* k    = (const float*)d_in[1];
    const float* v    = (const float*)d_in[2];
    const float* pos  = (const float*)d_in[3];
    const float* mask = (const float*)d_in[4];
    const float* Wq = (const float*)d_in[5];  const float* bq = (const float*)d_in[6];
    const float* Wk = (const float*)d_in[7];  const float* bk = (const float*)d_in[8];
    const float* Wv = (const float*)d_in[9];  const float* bv = (const float*)d_in[10];
    const float* Wp = (const float*)d_in[11]; const float* bp = (const float*)d_in[12];
    const float* Wo = (const float*)d_in[13]; const float* bo = (const float*)d_in[14];

    float* out = (float*)d_out;
    float* weights = out + (size_t)BATCH * SEQ * HID;

    float *QP, *KPK, *Vd, *O;
    cudaGetSymbolAddress((void**)&QP,  g_QP);
    cudaGetSymbolAddress((void**)&KPK, g_KPK);
    cudaGetSymbolAddress((void**)&Vd,  g_V);
    cudaGetSymbolAddress((void**)&O,   g_O);

    const int SMEM_BIG = 2 * (2 * 128 * 64 + 2 * 128 * 64);  // 65536
    const int SMEM_AV  = 2 * (2 * 128 * 64 + 2 * 64 * 64);   // 49152
    cudaFuncSetAttribute((const void*)mma_gemm<128, 0, false>,
                         cudaFuncAttributeMaxDynamicSharedMemorySize, SMEM_BIG);
    cudaFuncSetAttribute((const void*)mma_gemm<128, 1, false>,
                         cudaFuncAttributeMaxDynamicSharedMemorySize, SMEM_BIG);
    cudaFuncSetAttribute((const void*)mma_gemm<128, 2, false>,
                         cudaFuncAttributeMaxDynamicSharedMemorySize, SMEM_BIG);
    cudaFuncSetAttribute((const void*)mma_gemm<128, 3, false>,
                         cudaFuncAttributeMaxDynamicSharedMemorySize, SMEM_BIG);
    cudaFuncSetAttribute((const void*)mma_gemm<64, 4, true>,
                         cudaFuncAttributeMaxDynamicSharedMemorySize, SMEM_AV);

    dim3 gproj(HID / 128, M_TOTAL / 128, 1);   // (8, 32)

    // Projections (NT GEMM vs weight matrices, bias fused, head scatter)
    mma_gemm<128, 1, false><<<gproj, 256, SMEM_BIG>>>(q,   Wq, bq, QP,  1024, 1024, 1024, 0, 0, 0);
    mma_gemm<128, 1, false><<<gproj, 256, SMEM_BIG>>>(pos, Wp, bp, QP,  1024, 1024, 1024, 0, 0, 64);
    mma_gemm<128, 1, false><<<gproj, 256, SMEM_BIG>>>(k,   Wk, bk, KPK, 1024, 1024, 1024, 0, 0, 64);
    mma_gemm<128, 2, false><<<gproj, 256, SMEM_BIG>>>(v,   Wv, bv, Vd,  1024, 1024, 1024, 0, 0, 0);

    kp_add<<<(BH * SEQ * 64) / 256, 256>>>();

    // Scores: per bh, [2048 x 2048], K=128, fused scale+mask
    dim3 gsc(SEQ / 128, SEQ / 128, BH);        // (16, 16, 32)
    mma_gemm<128, 3, false><<<gsc, 256, SMEM_BIG>>>(QP, KPK, mask, weights,
                                                    128, 128, 128,
                                                    (long long)SEQ * 128,
                                                    (long long)SEQ * 128, 0);

    softmax_rows<<<BH * SEQ, 256>>>(weights);

    // AV: per bh, [2048 x 64], K=2048 (V transposed on the fly)
    dim3 gav(1, SEQ / 128, BH);                // (1, 16, 32)
    mma_gemm<64, 4, true><<<gav, 256, SMEM_AV>>>(weights, Vd, nullptr, O,
                                                 2048, 2048, 64,
                                                 (long long)SEQ * SEQ,
                                                 (long long)SEQ * 64, 0);

    // Final projection
    mma_gemm<128, 0, false><<<gproj, 256, SMEM_BIG>>>(O, Wo, bo, out,
                                                      1024, 1024, 1024, 0, 0, 0);
}

// round 8
// speedup vs baseline: 2.6126x; 1.0980x over previous
#include <cuda_runtime.h>
#include <cuda_bf16.h>
#include <cstdint>

#define NUM_HEADS 16
#define SEQ 2048
#define HID 1024
#define BATCH 2
#define M_TOTAL 4096
#define BH 32
#define SCALEF 0.125f

typedef __nv_bfloat16 bf16;

#define IN_ELEMS ((size_t)M_TOTAL * HID)    // 4M per input tensor
#define W_ELEMS  ((size_t)HID * HID)        // 1M per weight matrix

// ---------------- bf16 hi/lo scratch (no cudaMalloc allowed) ---------------
__device__ __align__(16) bf16 g_inhi[4 * IN_ELEMS], g_inlo[4 * IN_ELEMS];   // q,k,v,pos
__device__ __align__(16) bf16 g_whi [5 * W_ELEMS],  g_wlo [5 * W_ELEMS];    // Wq,Wk,Wv,Wp,Wo
__device__ __align__(16) bf16 g_QPhi [(size_t)BH * SEQ * 128], g_QPlo [(size_t)BH * SEQ * 128];
__device__ __align__(16) bf16 g_KPKhi[(size_t)BH * SEQ * 128], g_KPKlo[(size_t)BH * SEQ * 128];
__device__ __align__(16) bf16 g_Vhi  [(size_t)BH * SEQ * 64],  g_Vlo  [(size_t)BH * SEQ * 64];
__device__ __align__(16) bf16 g_Vthi [(size_t)BH * 64 * SEQ],  g_Vtlo [(size_t)BH * 64 * SEQ];
__device__ __align__(16) bf16 g_Ohi  [(size_t)M_TOTAL * HID],  g_Olo  [(size_t)M_TOTAL * HID];
__device__ __align__(16) bf16 g_Smhi [(size_t)BH * SEQ * SEQ], g_Smlo [(size_t)BH * SEQ * SEQ];

// ============================ PTX helpers ==================================
__device__ __forceinline__ uint32_t smem_u32(const void* p) {
    uint32_t a;
    asm("{ .reg .u64 t; cvta.to.shared.u64 t, %1; cvt.u32.u64 %0, t; }"
        : "=r"(a) : "l"(p));
    return a;
}

__device__ __forceinline__ void ldsm4(uint32_t& r0, uint32_t& r1,
                                      uint32_t& r2, uint32_t& r3, uint32_t addr) {
    asm volatile("ldmatrix.sync.aligned.m8n8.x4.shared.b16 {%0,%1,%2,%3}, [%4];"
                 : "=r"(r0), "=r"(r1), "=r"(r2), "=r"(r3) : "r"(addr));
}

__device__ __forceinline__ void mma16816(float* d, const uint32_t* a, const uint32_t* b) {
    asm volatile(
        "mma.sync.aligned.m16n8k16.row.col.f32.bf16.bf16.f32 "
        "{%0,%1,%2,%3},{%4,%5,%6,%7},{%8,%9},{%0,%1,%2,%3};"
        : "+f"(d[0]), "+f"(d[1]), "+f"(d[2]), "+f"(d[3])
        : "r"(a[0]), "r"(a[1]), "r"(a[2]), "r"(a[3]), "r"(b[0]), "r"(b[1]));
}

__device__ __forceinline__ void cpa16(uint32_t dst, const void* src) {
    asm volatile("cp.async.cg.shared.global [%0], [%1], 16;"
                 :: "r"(dst), "l"(src));
}
#define CPA_COMMIT() asm volatile("cp.async.commit_group;")
#define CPA_WAIT2()  asm volatile("cp.async.wait_group 2;")

// 64B rows, 4 chunks of 16B, chunk XOR (row>>1)&3
__device__ __forceinline__ uint32_t swz(int row, int kchunk) {
    return (uint32_t)(row * 64 + ((kchunk ^ ((row >> 1) & 3)) << 4));
}

// split helper: v -> (hi, lo) bf16x2 packed
__device__ __forceinline__ void split2(float v0, float v1, uint32_t& hi, uint32_t& lo) {
    __nv_bfloat162 h2 = __float22bfloat162_rn(make_float2(v0, v1));
    float2 hf = __bfloat1622float2(h2);
    __nv_bfloat162 l2 = __float22bfloat162_rn(make_float2(v0 - hf.x, v1 - hf.y));
    hi = *(uint32_t*)&h2;
    lo = *(uint32_t*)&l2;
}

// ====================== unified HMMA GEMM core (bf16x3) ====================
// C[m,n] = sum_k A[m,k]*B[n,k], A/B pre-split bf16 hi/lo, K-major rows.
// CTA tile 128 x BN, BK=32, 4-stage cp.async pipeline, 256 thr (8 warps).
// EPI: 0 fp32 out (+bias); 1 heads scatter bf16 hi/lo (+bias, rw/eoff);
//      3 scores fp32 (scale+mask); 4 AV -> O bf16 hi/lo
template<int BN, int EPI>
__device__ __forceinline__ void gemm_core(
    const bf16* __restrict__ Ahi, const bf16* __restrict__ Alo, int lda,
    const bf16* __restrict__ Bhi, const bf16* __restrict__ Blo, int ldb,
    const float* __restrict__ aux, float* __restrict__ dstf,
    bf16* __restrict__ dsthi, bf16* __restrict__ dstlo,
    int K, int rw, int eoff)
{
    extern __shared__ char smem[];
    constexpr int ATB = 128 * 64;
    constexpr int BTB = BN * 64;
    constexpr int STG = 2 * ATB + 2 * BTB;
    constexpr int WARPS_M = (BN == 128) ? 2 : 4;
    constexpr int WM = 128 / WARPS_M;
    constexpr int WN = BN / (8 / WARPS_M);
    constexpr int MT = WM / 16;
    constexpr int NT = WN / 8;

    const int tid = threadIdx.x, wid = tid >> 5, lane = tid & 31;
    const int g = lane >> 2, tig = lane & 3;
    const int wm = wid % WARPS_M, wn = wid / WARPS_M;
    const int m0 = blockIdx.y * 128, n0 = blockIdx.x * BN, bh = blockIdx.z;
    const uint32_t sb = smem_u32(smem);

    const int nch = K >> 5;

    auto issue = [&](int s) {
        const int kt = s * 32;
        const uint32_t st = sb + (s & 3) * STG;
#pragma unroll
        for (int it = 0; it < 2; it++) {
            int i = tid + it * 256;          // 512 chunks: 128 rows x 4
            int r = i >> 2, c = i & 3;
            uint32_t d0 = st + swz(r, c);
            size_t go = (size_t)r * lda + kt + c * 8;
            cpa16(d0, Ahi + go);
            cpa16(d0 + ATB, Alo + go);
        }
#pragma unroll
        for (int it = 0; it < BN / 64; it++) {
            int i = tid + it * 256;
            int r = i >> 2, c = i & 3;
            uint32_t d0 = st + 2 * ATB + swz(r, c);
            size_t go = (size_t)r * ldb + kt + c * 8;
            cpa16(d0, Bhi + go);
            cpa16(d0 + BTB, Blo + go);
        }
        CPA_COMMIT();
    };

    issue(0); issue(1); issue(2);

    float acc[MT][NT][4];
#pragma unroll
    for (int i = 0; i < MT; i++)
#pragma unroll
        for (int j = 0; j < NT; j++)
#pragma unroll
            for (int e = 0; e < 4; e++) acc[i][j][e] = 0.f;

    for (int c = 0; c < nch; c++) {
        CPA_WAIT2();
        __syncthreads();
        const uint32_t sA = sb + (c & 3) * STG;
        const uint32_t sB = sA + 2 * ATB;

#pragma unroll
        for (int ks = 0; ks < 2; ks++) {
            const int k0 = ks * 16;
            uint32_t ah[MT][4], al[MT][4], bhf[NT][2], blf[NT][2];
#pragma unroll
            for (int mt = 0; mt < MT; mt++) {
                const int sub = lane >> 3;
                const int row = wm * WM + mt * 16 + (lane & 7) + ((sub & 1) << 3);
                const int kk = k0 + ((sub >> 1) << 3);
                const uint32_t addr = sA + swz(row, kk >> 3);
                ldsm4(ah[mt][0], ah[mt][1], ah[mt][2], ah[mt][3], addr);
                ldsm4(al[mt][0], al[mt][1], al[mt][2], al[mt][3], addr + ATB);
            }
#pragma unroll
            for (int np = 0; np < NT / 2; np++) {
                const int sub = lane >> 3;
                const int row = wn * WN + np * 16 + (lane & 7) + ((sub >> 1) << 3);
                const int kk = k0 + ((sub & 1) << 3);
                const uint32_t addr = sB + swz(row, kk >> 3);
                uint32_t r0, r1, r2, r3;
                ldsm4(r0, r1, r2, r3, addr);
                bhf[np * 2][0] = r0; bhf[np * 2][1] = r1;
                bhf[np * 2 + 1][0] = r2; bhf[np * 2 + 1][1] = r3;
                ldsm4(r0, r1, r2, r3, addr + BTB);
                blf[np * 2][0] = r0; blf[np * 2][1] = r1;
                blf[np * 2 + 1][0] = r2; blf[np * 2 + 1][1] = r3;
            }
#pragma unroll
            for (int mt = 0; mt < MT; mt++)
#pragma unroll
                for (int nt = 0; nt < NT; nt++) {
                    mma16816(acc[mt][nt], ah[mt], bhf[nt]);
                    mma16816(acc[mt][nt], ah[mt], blf[nt]);
                    mma16816(acc[mt][nt], al[mt], bhf[nt]);
                }
        }

        if (c + 3 < nch) issue(c + 3);
        else CPA_COMMIT();
    }

    // ------------------------------ epilogue -------------------------------
#pragma unroll
    for (int mt = 0; mt < MT; mt++)
#pragma unroll
        for (int nt = 0; nt < NT; nt++) {
            const int ncol = n0 + wn * WN + nt * 8 + tig * 2;
#pragma unroll
            for (int half = 0; half < 2; half++) {
                const int m = m0 + wm * WM + mt * 16 + g + half * 8;
                float v0 = acc[mt][nt][half * 2 + 0];
                float v1 = acc[mt][nt][half * 2 + 1];
                if (EPI == 0) {
                    v0 += aux[ncol]; v1 += aux[ncol + 1];
                    *(float2*)(dstf + (size_t)m * HID + ncol) = make_float2(v0, v1);
                } else if (EPI == 1) {
                    v0 += aux[ncol]; v1 += aux[ncol + 1];
                    int b = m >> 11, s = m & 2047, h = ncol >> 6, d = ncol & 63;
                    size_t idx = ((size_t)(b * NUM_HEADS + h) * SEQ + s) * rw + eoff + d;
                    uint32_t hi, lo;
                    split2(v0, v1, hi, lo);
                    *(uint32_t*)(dsthi + idx) = hi;
                    *(uint32_t*)(dstlo + idx) = lo;
                } else if (EPI == 3) {
                    const float* mrow = aux + (size_t)m * SEQ + ncol;
                    size_t idx = (size_t)bh * SEQ * SEQ + (size_t)m * SEQ + ncol;
                    *(float2*)(dstf + idx) =
                        make_float2(v0 * SCALEF + mrow[0], v1 * SCALEF + mrow[1]);
                } else {  // EPI == 4: AV -> O bf16 hi/lo
                    int b = bh >> 4, h = bh & 15;
                    size_t idx = ((size_t)(b * SEQ + m)) * HID + h * 64 + ncol;
                    uint32_t hi, lo;
                    split2(v0, v1, hi, lo);
                    *(uint32_t*)(dsthi + idx) = hi;
                    *(uint32_t*)(dstlo + idx) = lo;
                }
            }
        }
}

// =========================== GEMM wrapper kernels ==========================
// z: 0=Q, 1=P, 2=K, 3=V (merged projections; grid (8, 32, 4))
__global__ __launch_bounds__(256) void k_proj(
    const float* __restrict__ bq, const float* __restrict__ bp,
    const float* __restrict__ bk, const float* __restrict__ bv)
{
    const int z = blockIdx.z;
    const bf16 *Ah, *Bh;
    const float* bias;
    bf16 *dh, *dl;
    int rw, eoff;
    switch (z) {
    case 0:  Ah = g_inhi;                Bh = g_whi;              bias = bq;
             dh = g_QPhi;  dl = g_QPlo;  rw = 128; eoff = 0;  break;
    case 1:  Ah = g_inhi + 3 * IN_ELEMS; Bh = g_whi + 3 * W_ELEMS; bias = bp;
             dh = g_QPhi;  dl = g_QPlo;  rw = 128; eoff = 64; break;
    case 2:  Ah = g_inhi + 1 * IN_ELEMS; Bh = g_whi + 1 * W_ELEMS; bias = bk;
             dh = g_KPKhi; dl = g_KPKlo; rw = 128; eoff = 64; break;
    default: Ah = g_inhi + 2 * IN_ELEMS; Bh = g_whi + 2 * W_ELEMS; bias = bv;
             dh = g_Vhi;   dl = g_Vlo;   rw = 64;  eoff = 0;  break;
    }
    const bf16* Al = g_inlo + (Ah - g_inhi);
    const bf16* Bl = g_wlo + (Bh - g_whi);
    size_t ao = (size_t)blockIdx.y * 128 * HID;
    size_t bo = (size_t)blockIdx.x * 128 * HID;
    gemm_core<128, 1>(Ah + ao, Al + ao, HID, Bh + bo, Bl + bo, HID,
                      bias, nullptr, dh, dl, HID, rw, eoff);
}

__global__ __launch_bounds__(256) void k_scores(
    const float* __restrict__ mask, float* __restrict__ weights)
{
    const int bh = blockIdx.z;
    size_t ao = ((size_t)bh * SEQ + blockIdx.y * 128) * 128;
    size_t bo = ((size_t)bh * SEQ + blockIdx.x * 128) * 128;
    gemm_core<128, 3>(g_QPhi + ao, g_QPlo + ao, 128,
                      g_KPKhi + bo, g_KPKlo + bo, 128,
                      mask, weights, nullptr, nullptr, 128, 0, 0);
}

__global__ __launch_bounds__(256) void k_av()
{
    const int bh = blockIdx.z;
    size_t ao = (size_t)bh * SEQ * SEQ + (size_t)blockIdx.y * 128 * SEQ;
    size_t bo = (size_t)bh * 64 * SEQ;
    gemm_core<64, 4>(g_Smhi + ao, g_Smlo + ao, SEQ,
                     g_Vthi + bo, g_Vtlo + bo, SEQ,
                     nullptr, nullptr, g_Ohi, g_Olo, SEQ, 0, 0);
}

__global__ __launch_bounds__(256) void k_final(
    const float* __restrict__ bo_, float* __restrict__ out)
{
    size_t ao = (size_t)blockIdx.y * 128 * HID;
    size_t bo = 4 * W_ELEMS + (size_t)blockIdx.x * 64 * HID;
    gemm_core<64, 0>(g_Ohi + ao, g_Olo + ao, HID,
                     g_whi + bo, g_wlo + bo, HID,
                     bo_, out, nullptr, nullptr, HID, 0, 0);
}

// ===================== converts / transpose / kp_add =======================
__global__ __launch_bounds__(256) void k_conv(
    const float* __restrict__ src, bf16* __restrict__ hi, bf16* __restrict__ lo, int n4)
{
    int i = blockIdx.x * 256 + threadIdx.x;
    if (i >= n4) return;
    float4 v = ((const float4*)src)[i];
    uint32_t h0, l0, h1, l1;
    split2(v.x, v.y, h0, l0);
    split2(v.z, v.w, h1, l1);
    ((uint2*)hi)[i] = make_uint2(h0, h1);
    ((uint2*)lo)[i] = make_uint2(l0, l1);
}

// KPK[:,0:64] = K + P (from bf16 hi/lo pairs, re-split)
__global__ __launch_bounds__(256) void k_kpadd()
{
    size_t i = (size_t)blockIdx.x * 256 + threadIdx.x;   // over BH*SEQ*32
    size_t r = i >> 5, j = i & 31;
    size_t src = r * 128 + 64 + j * 2;
    float2 kh = __bfloat1622float2(*(__nv_bfloat162*)&g_KPKhi[src]);
    float2 kl = __bfloat1622float2(*(__nv_bfloat162*)&g_KPKlo[src]);
    float2 ph = __bfloat1622float2(*(__nv_bfloat162*)&g_QPhi[src]);
    float2 pl = __bfloat1622float2(*(__nv_bfloat162*)&g_QPlo[src]);
    float s0 = kh.x + kl.x + ph.x + pl.x;
    float s1 = kh.y + kl.y + ph.y + pl.y;
    uint32_t hi, lo;
    split2(s0, s1, hi, lo);
    size_t dst = r * 128 + j * 2;
    *(uint32_t*)&g_KPKhi[dst] = hi;
    *(uint32_t*)&g_KPKlo[dst] = lo;
}

// V [bh][s][64] -> Vt [bh][d][2048] (both hi & lo), 64x64 SMEM tiles
__global__ __launch_bounds__(256) void k_vtrans()
{
    __shared__ bf16 th[64][65], tl[64][65];
    const int bh = blockIdx.y, s0 = blockIdx.x * 64;
    const int tid = threadIdx.x;
    const bf16* sh = g_Vhi + ((size_t)bh * SEQ + s0) * 64;
    const bf16* sl = g_Vlo + ((size_t)bh * SEQ + s0) * 64;
#pragma unroll
    for (int it = 0; it < 16; it++) {
        int i = tid + it * 256;
        int s = i >> 6, d = i & 63;
        th[s][d] = sh[(size_t)s * 64 + d];
        tl[s][d] = sl[(size_t)s * 64 + d];
    }
    __syncthreads();
    bf16* dh = g_Vthi + (size_t)bh * 64 * SEQ + s0;
    bf16* dl = g_Vtlo + (size_t)bh * 64 * SEQ + s0;
#pragma unroll
    for (int it = 0; it < 16; it++) {
        int i = tid + it * 256;
        int d = i >> 6, j = i & 63;
        dh[(size_t)d * SEQ + j] = th[j][d];
        dl[(size_t)d * SEQ + j] = tl[j][d];
    }
}

// softmax: fp32 in/out + bf16 hi/lo copy for the AV GEMM
__global__ __launch_bounds__(256) void softmax_rows(float* __restrict__ w)
{
    __shared__ float red[256];
    const size_t row = blockIdx.x;
    float* p = w + row * (size_t)SEQ;
    bf16* phi = g_Smhi + row * (size_t)SEQ;
    bf16* plo = g_Smlo + row * (size_t)SEQ;
    const int tid = threadIdx.x;

    float v[8];
    float mx = -1e30f;
#pragma unroll
    for (int i = 0; i < 8; i++) {
        v[i] = p[tid + i * 256];
        mx = fmaxf(mx, v[i]);
    }
    red[tid] = mx;
    __syncthreads();
    for (int s = 128; s > 0; s >>= 1) {
        if (tid < s) red[tid] = fmaxf(red[tid], red[tid + s]);
        __syncthreads();
    }
    mx = red[0];
    __syncthreads();

    float sum = 0.f;
#pragma unroll
    for (int i = 0; i < 8; i++) {
        v[i] = __expf(v[i] - mx);
        sum += v[i];
    }
    red[tid] = sum;
    __syncthreads();
    for (int s = 128; s > 0; s >>= 1) {
        if (tid < s) red[tid] += red[tid + s];
        __syncthreads();
    }
    float inv = 1.f / red[0];
#pragma unroll
    for (int i = 0; i < 8; i++) {
        float w_ = v[i] * inv;
        int c = tid + i * 256;
        p[c] = w_;
        bf16 h = __float2bfloat16(w_);
        phi[c] = h;
        plo[c] = __float2bfloat16(w_ - __bfloat162float(h));
    }
}

// ===========================================================================
extern "C" void kernel_launch(void* const* d_in, const int* in_sizes, int n_in,
                              void* d_out, int out_size)
{
    const float* q    = (const float*)d_in[0];
    const float* k    = (const float*)d_in[1];
    const float* v    = (const float*)d_in[2];
    const float* pos  = (const float*)d_in[3];
    const float* mask = (const float*)d_in[4];
    const float* Wq = (const float*)d_in[5];  const float* bq = (const float*)d_in[6];
    const float* Wk = (const float*)d_in[7];  const float* bk = (const float*)d_in[8];
    const float* Wv = (const float*)d_in[9];  const float* bv = (const float*)d_in[10];
    const float* Wp = (const float*)d_in[11]; const float* bp = (const float*)d_in[12];
    const float* Wo = (const float*)d_in[13]; const float* bo = (const float*)d_in[14];

    float* out = (float*)d_out;
    float* weights = out + (size_t)BATCH * SEQ * HID;

    bf16 *inhi, *inlo, *whi, *wlo;
    cudaGetSymbolAddress((void**)&inhi, g_inhi);
    cudaGetSymbolAddress((void**)&inlo, g_inlo);
    cudaGetSymbolAddress((void**)&whi,  g_whi);
    cudaGetSymbolAddress((void**)&wlo,  g_wlo);

    const int SMEM_128 = 4 * (2 * 128 * 64 + 2 * 128 * 64);  // 131072
    const int SMEM_64  = 4 * (2 * 128 * 64 + 2 * 64 * 64);   //  98304
    cudaFuncSetAttribute((const void*)k_proj,
                         cudaFuncAttributeMaxDynamicSharedMemorySize, SMEM_128);
    cudaFuncSetAttribute((const void*)k_scores,
                         cudaFuncAttributeMaxDynamicSharedMemorySize, SMEM_128);
    cudaFuncSetAttribute((const void*)k_av,
                         cudaFuncAttributeMaxDynamicSharedMemorySize, SMEM_64);
    cudaFuncSetAttribute((const void*)k_final,
                         cudaFuncAttributeMaxDynamicSharedMemorySize, SMEM_64);

    // 1) convert raw fp32 inputs / weights to bf16 hi/lo
    const int N4_IN = (int)(IN_ELEMS / 4), N4_W = (int)(W_ELEMS / 4);
    k_conv<<<(N4_IN + 255) / 256, 256>>>(q,   inhi + 0 * IN_ELEMS, inlo + 0 * IN_ELEMS, N4_IN);
    k_conv<<<(N4_IN + 255) / 256, 256>>>(k,   inhi + 1 * IN_ELEMS, inlo + 1 * IN_ELEMS, N4_IN);
    k_conv<<<(N4_IN + 255) / 256, 256>>>(v,   inhi + 2 * IN_ELEMS, inlo + 2 * IN_ELEMS, N4_IN);
    k_conv<<<(N4_IN + 255) / 256, 256>>>(pos, inhi + 3 * IN_ELEMS, inlo + 3 * IN_ELEMS, N4_IN);
    k_conv<<<(N4_W + 255) / 256, 256>>>(Wq, whi + 0 * W_ELEMS, wlo + 0 * W_ELEMS, N4_W);
    k_conv<<<(N4_W + 255) / 256, 256>>>(Wk, whi + 1 * W_ELEMS, wlo + 1 * W_ELEMS, N4_W);
    k_conv<<<(N4_W + 255) / 256, 256>>>(Wv, whi + 2 * W_ELEMS, wlo + 2 * W_ELEMS, N4_W);
    k_conv<<<(N4_W + 255) / 256, 256>>>(Wp, whi + 3 * W_ELEMS, wlo + 3 * W_ELEMS, N4_W);
    k_conv<<<(N4_W + 255) / 256, 256>>>(Wo, whi + 4 * W_ELEMS, wlo + 4 * W_ELEMS, N4_W);

    // 2) merged projections (Q, P, K, V) — grid (8, 32, 4)
    k_proj<<<dim3(HID / 128, M_TOTAL / 128, 4), 256, SMEM_128>>>(bq, bp, bk, bv);

    // 3) KPK[:,0:64] = K + P
    k_kpadd<<<(BH * SEQ * 32) / 256, 256>>>();

    // 4) V transpose for AV B-operand
    k_vtrans<<<dim3(SEQ / 64, BH), 256>>>();

    // 5) scores (scale + mask fused)
    k_scores<<<dim3(SEQ / 128, SEQ / 128, BH), 256, SMEM_128>>>(mask, weights);

    // 6) softmax (+ bf16 hi/lo copy)
    softmax_rows<<<BH * SEQ, 256>>>(weights);

    // 7) AV
    k_av<<<dim3(1, SEQ / 128, BH), 256, SMEM_64>>>();

    // 8) final projection
    k_final<<<dim3(HID / 64, M_TOTAL / 128), 256, SMEM_64>>>(bo, out);
}